// round 3
// baseline (speedup 1.0000x reference)
#include <cuda_runtime.h>
#include <cuda_bf16.h>

#define L 128

// out[(bq*L + j)*L + i] = sum_k trilinear(density[b], base + i*R0 + j*R1 + k*R2)
// where Rc = rotation[b][q][c][:], base_m = 63.5*(1 - (R0m+R1m+R2m)).
__global__ __launch_bounds__(128)
void proj_kernel(const float* __restrict__ density,
                 const float* __restrict__ rot,
                 float* __restrict__ out)
{
    const int i  = threadIdx.x;     // X (fast output dim)
    const int j  = blockIdx.x;      // Y
    const int bq = blockIdx.y;      // b*8 + q  (0..31)
    const int b  = bq >> 3;

    const float* R = rot + bq * 9;  // row-major [c][m]
    const float R00 = R[0], R01 = R[1], R02 = R[2];   // per-i step
    const float R10 = R[3], R11 = R[4], R12 = R[5];   // per-j step
    const float R20 = R[6], R21 = R[7], R22 = R[8];   // per-k step

    const float* __restrict__ vol = density + (size_t)b * (L * L * L);

    // base point for this pixel (k = 0)
    const float bx = fmaf((float)i, R00, fmaf((float)j, R10, 63.5f * (1.0f - (R00 + R10 + R20))));
    const float by = fmaf((float)i, R01, fmaf((float)j, R11, 63.5f * (1.0f - (R01 + R11 + R21))));
    const float bz = fmaf((float)i, R02, fmaf((float)j, R12, 63.5f * (1.0f - (R02 + R12 + R22))));

    float acc = 0.0f;

    #pragma unroll 4
    for (int k = 0; k < L; ++k) {
        const float kf = (float)k;
        const float px = fmaf(kf, R20, bx);
        const float py = fmaf(kf, R21, by);
        const float pz = fmaf(kf, R22, bz);

        const float fx0 = floorf(px), fy0 = floorf(py), fz0 = floorf(pz);
        const int x0 = (int)fx0, y0 = (int)fy0, z0 = (int)fz0;
        const float fx = px - fx0, fy = py - fy0, fz = pz - fz0;

        float c000, c100, c010, c110, c001, c101, c011, c111;

        if ((unsigned)x0 < (unsigned)(L - 1) &&
            (unsigned)y0 < (unsigned)(L - 1) &&
            (unsigned)z0 < (unsigned)(L - 1)) {
            // fast path: whole 2x2x2 cell in bounds
            const float* p = vol + ((z0 * L + y0) * L + x0);
            c000 = __ldg(p);         c100 = __ldg(p + 1);
            c010 = __ldg(p + L);     c110 = __ldg(p + L + 1);
            p += L * L;
            c001 = __ldg(p);         c101 = __ldg(p + 1);
            c011 = __ldg(p + L);     c111 = __ldg(p + L + 1);
        } else {
            // boundary: per-corner zero padding
            const int x1 = x0 + 1, y1 = y0 + 1, z1 = z0 + 1;
            const bool vx0 = (unsigned)x0 < (unsigned)L, vx1 = (unsigned)x1 < (unsigned)L;
            const bool vy0 = (unsigned)y0 < (unsigned)L, vy1 = (unsigned)y1 < (unsigned)L;
            const bool vz0 = (unsigned)z0 < (unsigned)L, vz1 = (unsigned)z1 < (unsigned)L;
            const int cx0 = vx0 ? x0 : 0, cx1 = vx1 ? x1 : 0;
            const int cy0 = vy0 ? y0 : 0, cy1 = vy1 ? y1 : 0;
            const int cz0 = vz0 ? z0 : 0, cz1 = vz1 ? z1 : 0;
            c000 = (vx0 && vy0 && vz0) ? __ldg(vol + ((cz0 * L + cy0) * L + cx0)) : 0.0f;
            c100 = (vx1 && vy0 && vz0) ? __ldg(vol + ((cz0 * L + cy0) * L + cx1)) : 0.0f;
            c010 = (vx0 && vy1 && vz0) ? __ldg(vol + ((cz0 * L + cy1) * L + cx0)) : 0.0f;
            c110 = (vx1 && vy1 && vz0) ? __ldg(vol + ((cz0 * L + cy1) * L + cx1)) : 0.0f;
            c001 = (vx0 && vy0 && vz1) ? __ldg(vol + ((cz1 * L + cy0) * L + cx0)) : 0.0f;
            c101 = (vx1 && vy0 && vz1) ? __ldg(vol + ((cz1 * L + cy0) * L + cx1)) : 0.0f;
            c011 = (vx0 && vy1 && vz1) ? __ldg(vol + ((cz1 * L + cy1) * L + cx0)) : 0.0f;
            c111 = (vx1 && vy1 && vz1) ? __ldg(vol + ((cz1 * L + cy1) * L + cx1)) : 0.0f;
        }

        // trilinear interpolation
        const float cx00 = fmaf(fx, c100 - c000, c000);
        const float cx10 = fmaf(fx, c110 - c010, c010);
        const float cx01 = fmaf(fx, c101 - c001, c001);
        const float cx11 = fmaf(fx, c111 - c011, c011);
        const float cxy0 = fmaf(fy, cx10 - cx00, cx00);
        const float cxy1 = fmaf(fy, cx11 - cx01, cx01);
        acc += fmaf(fz, cxy1 - cxy0, cxy0);
    }

    out[((size_t)bq * L + j) * L + i] = acc;
}

extern "C" void kernel_launch(void* const* d_in, const int* in_sizes, int n_in,
                              void* d_out, int out_size)
{
    const float* density = (const float*)d_in[0];   // (4,128,128,128)
    const float* rot     = (const float*)d_in[1];   // (4,8,3,3)
    float* out           = (float*)d_out;           // (4,8,128,128)

    dim3 grid(L, 32);   // j, b*q
    dim3 block(L);      // i
    proj_kernel<<<grid, block>>>(density, rot, out);
}

// round 4
// speedup vs baseline: 1.5198x; 1.5198x over previous
#include <cuda_runtime.h>
#include <cuda_bf16.h>

#define L   128
#define PD  130                 // padded dim (1-voxel zero apron each side)
#define PS  (PD * PD)           // padded slice stride (entries)
#define PV  (PD * PD * PD)      // padded volume entries

// Padded pair-packed volumes: pad[b][(zp*PD+yp)*PD+xp] = (v[x0], v[x0+1]),
// zero outside the real volume. x0 = xp-1, etc. float2 -> every entry 8B aligned.
__device__ float2 g_pad[4][PV];

__global__ __launch_bounds__(160)
void fill_pad_kernel(const float* __restrict__ density)
{
    const int xp = threadIdx.x;
    if (xp >= PD) return;
    const int yp = blockIdx.x;   // 0..129
    const int zp = blockIdx.y;   // 0..129
    const int b  = blockIdx.z;   // 0..3

    const int x0 = xp - 1, y0 = yp - 1, z0 = zp - 1;
    const bool rowv = ((unsigned)y0 < (unsigned)L) && ((unsigned)z0 < (unsigned)L);

    float v0 = 0.0f, v1 = 0.0f;
    if (rowv) {
        const float* row = density + ((size_t)b * L * L * L) + ((size_t)(z0 * L + y0) * L);
        if ((unsigned)x0 < (unsigned)L)       v0 = row[x0];
        if ((unsigned)(x0 + 1) < (unsigned)L) v1 = row[x0 + 1];
    }
    g_pad[b][(zp * PD + yp) * PD + xp] = make_float2(v0, v1);
}

__global__ __launch_bounds__(128)
void proj_kernel(const float* __restrict__ rot,
                 float* __restrict__ out)
{
    const int bq = blockIdx.y;      // b*8 + q
    const int b  = bq >> 3;

    const float* R = rot + bq * 9;  // row-major [c][m]
    const float R00 = R[0], R01 = R[1], R02 = R[2];   // i-step
    const float R10 = R[3], R11 = R[4], R12 = R[5];   // j-step
    const float R20 = R[6], R21 = R[7], R22 = R[8];   // k-step (ray dir)

    // Adaptive lane axis: lanes walk the step vector with the smaller (y,z)
    // footprint -> fewer distinct 128B lines per warp gather.
    const bool lanes_j = fmaxf(fabsf(R11), fabsf(R12)) < fmaxf(fabsf(R01), fabsf(R02));
    const int i = lanes_j ? blockIdx.x : threadIdx.x;
    const int j = lanes_j ? threadIdx.x : blockIdx.x;

    const float2* __restrict__ pad = g_pad[b];

    // base point for this pixel (k = 0):  63.5*(2/127) == 1 exactly
    const float bx = fmaf((float)i, R00, fmaf((float)j, R10, 63.5f * (1.0f - (R00 + R10 + R20))));
    const float by = fmaf((float)i, R01, fmaf((float)j, R11, 63.5f * (1.0f - (R01 + R11 + R21))));
    const float bz = fmaf((float)i, R02, fmaf((float)j, R12, 63.5f * (1.0f - (R02 + R12 + R22))));

    // Ray-box clipping: shrink k range to where the ray can touch the padded
    // box. Correctness is still enforced by the in-loop guard; this only
    // removes provably-zero iterations.
    float kmin = 0.0f, kmax = 127.0f;
    {
        #pragma unroll
        for (int m = 0; m < 3; ++m) {
            const float bm = (m == 0) ? bx : (m == 1) ? by : bz;
            const float rm = (m == 0) ? R20 : (m == 1) ? R21 : R22;
            if (fabsf(rm) > 1e-9f) {
                const float inv = 1.0f / rm;
                const float t0 = (-1.0f - bm) * inv;
                const float t1 = (129.0f - bm) * inv;
                kmin = fmaxf(kmin, fminf(t0, t1));
                kmax = fminf(kmax, fmaxf(t0, t1));
            } else if (bm <= -1.0f || bm >= 129.0f) {
                kmax = -1.0f;
            }
        }
    }
    const int k0 = (int)fmaxf(0.0f,   floorf(kmin) - 1.0f);
    const int k1 = (int)fminf(127.0f, ceilf(kmax)  + 1.0f);

    float acc = 0.0f;

    #pragma unroll 4
    for (int k = k0; k <= k1; ++k) {
        const float kf = (float)k;
        const float px = fmaf(kf, R20, bx);
        const float py = fmaf(kf, R21, by);
        const float pz = fmaf(kf, R22, bz);

        const float fx0 = floorf(px), fy0 = floorf(py), fz0 = floorf(pz);
        const int xp = (int)fx0 + 1;   // padded coords
        const int yp = (int)fy0 + 1;
        const int zp = (int)fz0 + 1;
        const float fx = px - fx0, fy = py - fy0, fz = pz - fz0;

        // Any sample with a possibly-nonzero contribution has xp,yp,zp in [0,128].
        if ((unsigned)xp <= 128u && (unsigned)yp <= 128u && (unsigned)zp <= 128u) {
            const int e = (zp * PD + yp) * PD + xp;
            const float2 a00 = __ldg(pad + e);
            const float2 a10 = __ldg(pad + e + PD);
            const float2 a01 = __ldg(pad + e + PS);
            const float2 a11 = __ldg(pad + e + PS + PD);

            const float cx00 = fmaf(fx, a00.y - a00.x, a00.x);
            const float cx10 = fmaf(fx, a10.y - a10.x, a10.x);
            const float cx01 = fmaf(fx, a01.y - a01.x, a01.x);
            const float cx11 = fmaf(fx, a11.y - a11.x, a11.x);
            const float cxy0 = fmaf(fy, cx10 - cx00, cx00);
            const float cxy1 = fmaf(fy, cx11 - cx01, cx01);
            acc += fmaf(fz, cxy1 - cxy0, cxy0);
        }
    }

    out[((size_t)bq * L + j) * L + i] = acc;
}

extern "C" void kernel_launch(void* const* d_in, const int* in_sizes, int n_in,
                              void* d_out, int out_size)
{
    const float* density = (const float*)d_in[0];   // (4,128,128,128)
    const float* rot     = (const float*)d_in[1];   // (4,8,3,3)
    float* out           = (float*)d_out;           // (4,8,128,128)

    // Pre-pass: build zero-apron pair-packed volumes (deterministic, every call).
    dim3 fgrid(PD, PD, 4);
    fill_pad_kernel<<<fgrid, 160>>>(density);

    dim3 grid(L, 32);   // (other output axis), b*q
    proj_kernel<<<grid, 128>>>(rot, out);
}

// round 5
// speedup vs baseline: 1.8847x; 1.2401x over previous
#include <cuda_runtime.h>
#include <cuda_bf16.h>

#define L   128
#define PD  130                 // padded dim (zero apron)
#define PS  (PD * PD)           // padded slice stride (entries)
#define PV  (PD * PD * PD)      // padded volume entries

// Quad-packed padded volumes:
//   g_quad[b][(zp*PD+yp)*PD+xp] = ( v(x0,y0,z), v(x0+1,y0,z), v(x0,y0+1,z), v(x0+1,y0+1,z) )
// with x0=xp-1, y0=yp-1, z=zp-1, zeros outside the real volume.
// One float4 = the full 2x2 xy-corner set at one z plane -> 2 LDG.128 per trilinear sample.
__device__ float4 g_quad[4][PV];

__global__ __launch_bounds__(160)
void fill_quad_kernel(const float* __restrict__ density, int b_base)
{
    const int xp = threadIdx.x;
    if (xp >= PD) return;
    const int yp = blockIdx.x;   // 0..129
    const int zp = blockIdx.y;   // 0..129
    const int b  = b_base + blockIdx.z;  // 2 volumes per launch

    const int x0 = xp - 1, y0 = yp - 1, z = zp - 1;
    float v00 = 0.f, v10 = 0.f, v01 = 0.f, v11 = 0.f;

    if ((unsigned)z < (unsigned)L) {
        const float* pl = density + ((size_t)b * L * L * L) + ((size_t)z * L * L);
        const bool vx0 = (unsigned)x0 < (unsigned)L;
        const bool vx1 = (unsigned)(x0 + 1) < (unsigned)L;
        if ((unsigned)y0 < (unsigned)L) {
            const float* r0 = pl + (size_t)y0 * L;
            if (vx0) v00 = __ldg(r0 + x0);
            if (vx1) v10 = __ldg(r0 + x0 + 1);
        }
        if ((unsigned)(y0 + 1) < (unsigned)L) {
            const float* r1 = pl + (size_t)(y0 + 1) * L;
            if (vx0) v01 = __ldg(r1 + x0);
            if (vx1) v11 = __ldg(r1 + x0 + 1);
        }
    }
    g_quad[b][(zp * PD + yp) * PD + xp] = make_float4(v00, v10, v01, v11);
}

__global__ __launch_bounds__(128)
void proj_kernel(const float* __restrict__ rot,
                 float* __restrict__ out, int bq_base)
{
    const int bq = bq_base + blockIdx.y;   // b*8 + q
    const int b  = bq >> 3;

    const float* R = rot + bq * 9;  // row-major [c][m]
    const float R00 = R[0], R01 = R[1], R02 = R[2];   // i-step
    const float R10 = R[3], R11 = R[4], R12 = R[5];   // j-step
    const float R20 = R[6], R21 = R[7], R22 = R[8];   // k-step (ray dir)

    // Lanes walk the step vector with smaller (y,z) footprint -> fewer lines/warp-load.
    const bool lanes_j = fmaxf(fabsf(R11), fabsf(R12)) < fmaxf(fabsf(R01), fabsf(R02));
    const int i = lanes_j ? blockIdx.x : threadIdx.x;
    const int j = lanes_j ? threadIdx.x : blockIdx.x;

    const float4* __restrict__ quad = g_quad[b];

    // base point for this pixel (k = 0):  63.5*(2/127) == 1 exactly
    const float bx = fmaf((float)i, R00, fmaf((float)j, R10, 63.5f * (1.0f - (R00 + R10 + R20))));
    const float by = fmaf((float)i, R01, fmaf((float)j, R11, 63.5f * (1.0f - (R01 + R11 + R21))));
    const float bz = fmaf((float)i, R02, fmaf((float)j, R12, 63.5f * (1.0f - (R02 + R12 + R22))));

    // Ray-box clip: only iterate k where the ray can intersect the padded box.
    float kmin = 0.0f, kmax = 127.0f;
    {
        #pragma unroll
        for (int m = 0; m < 3; ++m) {
            const float bm = (m == 0) ? bx : (m == 1) ? by : bz;
            const float rm = (m == 0) ? R20 : (m == 1) ? R21 : R22;
            if (fabsf(rm) > 1e-9f) {
                const float inv = 1.0f / rm;
                const float t0 = (-1.0f - bm) * inv;
                const float t1 = (129.0f - bm) * inv;
                kmin = fmaxf(kmin, fminf(t0, t1));
                kmax = fminf(kmax, fmaxf(t0, t1));
            } else if (bm <= -1.0f || bm >= 129.0f) {
                kmax = -1.0f;
            }
        }
    }
    const int k0 = (int)fmaxf(0.0f,   floorf(kmin) - 1.0f);
    const int k1 = (int)fminf(127.0f, ceilf(kmax)  + 1.0f);

    float acc = 0.0f;

    #pragma unroll 4
    for (int k = k0; k <= k1; ++k) {
        const float kf = (float)k;
        const float px = fmaf(kf, R20, bx);
        const float py = fmaf(kf, R21, by);
        const float pz = fmaf(kf, R22, bz);

        const float fx0 = floorf(px), fy0 = floorf(py), fz0 = floorf(pz);
        const int xp = (int)fx0 + 1;   // padded coords
        const int yp = (int)fy0 + 1;
        const int zp = (int)fz0 + 1;
        const float fx = px - fx0, fy = py - fy0, fz = pz - fz0;

        // Any possibly-nonzero sample has xp,yp,zp in [0,128]; zp+1 <= 129 in-array.
        if ((unsigned)xp <= 128u && (unsigned)yp <= 128u && (unsigned)zp <= 128u) {
            const int e = (zp * PD + yp) * PD + xp;
            const float4 a0 = __ldg(quad + e);        // z0 plane: 2x2 xy corners
            const float4 a1 = __ldg(quad + e + PS);   // z1 plane

            const float c0x0 = fmaf(fx, a0.y - a0.x, a0.x);
            const float c0x1 = fmaf(fx, a0.w - a0.z, a0.z);
            const float c0   = fmaf(fy, c0x1 - c0x0, c0x0);
            const float c1x0 = fmaf(fx, a1.y - a1.x, a1.x);
            const float c1x1 = fmaf(fx, a1.w - a1.z, a1.z);
            const float c1   = fmaf(fy, c1x1 - c1x0, c1x0);
            acc += fmaf(fz, c1 - c0, c0);
        }
    }

    out[((size_t)bq * L + j) * L + i] = acc;
}

extern "C" void kernel_launch(void* const* d_in, const int* in_sizes, int n_in,
                              void* d_out, int out_size)
{
    const float* density = (const float*)d_in[0];   // (4,128,128,128)
    const float* rot     = (const float*)d_in[1];   // (4,8,3,3)
    float* out           = (float*)d_out;           // (4,8,128,128)

    // Phase volumes in pairs so each phase's 70MB quad working set is
    // L2-resident (write-back fill -> proj reads hit L2, not DRAM).
    dim3 fgrid(PD, PD, 2);
    dim3 pgrid(L, 16);

    fill_quad_kernel<<<fgrid, 160>>>(density, 0);
    proj_kernel<<<pgrid, 128>>>(rot, out, 0);
    fill_quad_kernel<<<fgrid, 160>>>(density, 2);
    proj_kernel<<<pgrid, 128>>>(rot, out, 16);
}

// round 6
// speedup vs baseline: 2.0343x; 1.0793x over previous
#include <cuda_runtime.h>
#include <cuda_fp16.h>
#include <cuda_bf16.h>

#define L   128
#define PD  130                 // padded dim (zero apron)
#define PS  (PD * PD)           // padded slice stride (entries)
#define PV  (PD * PD * PD)      // padded volume entries

// Oct-packed padded volumes (fp16): one 16B entry per cell holds all 8 corners.
//   entry.x = half2( v(x0,y0,z0), v(x1,y0,z0) )
//   entry.y = half2( v(x0,y1,z0), v(x1,y1,z0) )
//   entry.z = half2( v(x0,y0,z1), v(x1,y0,z1) )
//   entry.w = half2( v(x0,y1,z1), v(x1,y1,z1) )
// with x0=xp-1, y0=yp-1, z0=zp-1, z1=z0+1; zeros outside the real volume.
// => ONE LDG.128 per trilinear sample.
__device__ uint4 g_oct[4][PV];

__device__ __forceinline__ unsigned pack2(float a, float b) {
    __half2 h = __floats2half2_rn(a, b);
    return *reinterpret_cast<unsigned*>(&h);
}

__global__ __launch_bounds__(160)
void fill_oct_kernel(const float* __restrict__ density, int b_base)
{
    const int xp = threadIdx.x;
    if (xp >= PD) return;
    const int yp = blockIdx.x;   // 0..129
    const int zp = blockIdx.y;   // 0..129
    const int b  = b_base + blockIdx.z;  // 2 volumes per launch

    const int x0 = xp - 1, y0 = yp - 1, z0 = zp - 1;
    const bool vx0 = (unsigned)x0 < (unsigned)L;
    const bool vx1 = (unsigned)(x0 + 1) < (unsigned)L;
    const bool vy0 = (unsigned)y0 < (unsigned)L;
    const bool vy1 = (unsigned)(y0 + 1) < (unsigned)L;

    const float* volb = density + (size_t)b * L * L * L;

    float v[2][2][2];  // [z][y][x]
    #pragma unroll
    for (int dz = 0; dz < 2; ++dz) {
        const int z = z0 + dz;
        const bool vz = (unsigned)z < (unsigned)L;
        const float* pl = volb + (size_t)(vz ? z : 0) * L * L;
        #pragma unroll
        for (int dy = 0; dy < 2; ++dy) {
            const bool vy = dy ? vy1 : vy0;
            const int y = y0 + dy;
            const float* row = pl + (size_t)(vy ? y : 0) * L;
            v[dz][dy][0] = (vz && vy && vx0) ? __ldg(row + x0)     : 0.0f;
            v[dz][dy][1] = (vz && vy && vx1) ? __ldg(row + x0 + 1) : 0.0f;
        }
    }

    uint4 e;
    e.x = pack2(v[0][0][0], v[0][0][1]);
    e.y = pack2(v[0][1][0], v[0][1][1]);
    e.z = pack2(v[1][0][0], v[1][0][1]);
    e.w = pack2(v[1][1][0], v[1][1][1]);
    g_oct[b][(zp * PD + yp) * PD + xp] = e;
}

__global__ __launch_bounds__(128)
void proj_kernel(const float* __restrict__ rot,
                 float* __restrict__ out, int bq_base)
{
    const int bq = bq_base + blockIdx.y;   // b*8 + q
    const int b  = bq >> 3;

    const float* R = rot + bq * 9;  // row-major [c][m]
    const float R00 = R[0], R01 = R[1], R02 = R[2];   // i-step
    const float R10 = R[3], R11 = R[4], R12 = R[5];   // j-step
    const float R20 = R[6], R21 = R[7], R22 = R[8];   // k-step (ray dir)

    // Lanes walk the step vector with smaller (y,z) footprint -> fewer lines/warp-load.
    const bool lanes_j = fmaxf(fabsf(R11), fabsf(R12)) < fmaxf(fabsf(R01), fabsf(R02));
    const int i = lanes_j ? blockIdx.x : threadIdx.x;
    const int j = lanes_j ? threadIdx.x : blockIdx.x;

    const uint4* __restrict__ oct = g_oct[b];

    // base point for this pixel (k = 0):  63.5*(2/127) == 1 exactly
    const float bx = fmaf((float)i, R00, fmaf((float)j, R10, 63.5f * (1.0f - (R00 + R10 + R20))));
    const float by = fmaf((float)i, R01, fmaf((float)j, R11, 63.5f * (1.0f - (R01 + R11 + R21))));
    const float bz = fmaf((float)i, R02, fmaf((float)j, R12, 63.5f * (1.0f - (R02 + R12 + R22))));

    // Ray-box clip: only iterate k where the ray can intersect the padded box.
    float kmin = 0.0f, kmax = 127.0f;
    {
        #pragma unroll
        for (int m = 0; m < 3; ++m) {
            const float bm = (m == 0) ? bx : (m == 1) ? by : bz;
            const float rm = (m == 0) ? R20 : (m == 1) ? R21 : R22;
            if (fabsf(rm) > 1e-9f) {
                const float inv = 1.0f / rm;
                const float t0 = (-1.0f - bm) * inv;
                const float t1 = (129.0f - bm) * inv;
                kmin = fmaxf(kmin, fminf(t0, t1));
                kmax = fminf(kmax, fmaxf(t0, t1));
            } else if (bm <= -1.0f || bm >= 129.0f) {
                kmax = -1.0f;
            }
        }
    }
    const int k0 = (int)fmaxf(0.0f,   floorf(kmin) - 1.0f);
    const int k1 = (int)fminf(127.0f, ceilf(kmax)  + 1.0f);

    float acc = 0.0f;

    #pragma unroll 4
    for (int k = k0; k <= k1; ++k) {
        const float kf = (float)k;
        const float px = fmaf(kf, R20, bx);
        const float py = fmaf(kf, R21, by);
        const float pz = fmaf(kf, R22, bz);

        const float fx0 = floorf(px), fy0 = floorf(py), fz0 = floorf(pz);
        const int xp = (int)fx0 + 1;   // padded coords
        const int yp = (int)fy0 + 1;
        const int zp = (int)fz0 + 1;
        const float fx = px - fx0, fy = py - fy0, fz = pz - fz0;

        // Any possibly-nonzero sample has xp,yp,zp in [0,128].
        if ((unsigned)xp <= 128u && (unsigned)yp <= 128u && (unsigned)zp <= 128u) {
            const uint4 r = __ldg(oct + (zp * PD + yp) * PD + xp);
            const float2 f00 = __half22float2(*reinterpret_cast<const __half2*>(&r.x)); // v000,v100
            const float2 f01 = __half22float2(*reinterpret_cast<const __half2*>(&r.y)); // v010,v110
            const float2 f10 = __half22float2(*reinterpret_cast<const __half2*>(&r.z)); // v001,v101
            const float2 f11 = __half22float2(*reinterpret_cast<const __half2*>(&r.w)); // v011,v111

            const float cx00 = fmaf(fx, f00.y - f00.x, f00.x);
            const float cx10 = fmaf(fx, f01.y - f01.x, f01.x);
            const float c0   = fmaf(fy, cx10 - cx00, cx00);
            const float cx01 = fmaf(fx, f10.y - f10.x, f10.x);
            const float cx11 = fmaf(fx, f11.y - f11.x, f11.x);
            const float c1   = fmaf(fy, cx11 - cx01, cx01);
            acc += fmaf(fz, c1 - c0, c0);
        }
    }

    out[((size_t)bq * L + j) * L + i] = acc;
}

extern "C" void kernel_launch(void* const* d_in, const int* in_sizes, int n_in,
                              void* d_out, int out_size)
{
    const float* density = (const float*)d_in[0];   // (4,128,128,128)
    const float* rot     = (const float*)d_in[1];   // (4,8,3,3)
    float* out           = (float*)d_out;           // (4,8,128,128)

    // Phase volumes in pairs so each phase's 70MB oct working set is
    // L2-resident (write-back fill -> proj reads hit L2, not DRAM).
    dim3 fgrid(PD, PD, 2);
    dim3 pgrid(L, 16);

    fill_oct_kernel<<<fgrid, 160>>>(density, 0);
    proj_kernel<<<pgrid, 128>>>(rot, out, 0);
    fill_oct_kernel<<<fgrid, 160>>>(density, 2);
    proj_kernel<<<pgrid, 128>>>(rot, out, 16);
}

// round 9
// speedup vs baseline: 2.1479x; 1.0558x over previous
#include <cuda_runtime.h>
#include <cuda_fp16.h>
#include <cuda_bf16.h>

#define L   128
#define PD  130                 // padded dim (zero apron)
#define PS  (PD * PD)
#define PV  (PD * PD * PD)

// Oct-packed padded volumes (fp16): one 16B entry per cell = all 8 corners.
//   e.x = half2(v(x0,y0,z0), v(x1,y0,z0)),  e.y = half2(v(x0,y1,z0), v(x1,y1,z0))
//   e.z = half2(v(x0,y0,z1), v(x1,y0,z1)),  e.w = half2(v(x0,y1,z1), v(x1,y1,z1))
// x0=xp-1 etc.; zeros outside the real volume. ONE LDG.128 per trilinear sample.
__device__ uint4 g_oct[4][PV];

__device__ __forceinline__ unsigned pack2(float a, float b) {
    __half2 h = __floats2half2_rn(a, b);
    return *reinterpret_cast<unsigned*>(&h);
}

// Each thread fills 4 consecutive xp entries: per (y,z) row it needs x values
// [xb-1, xb+3] = one aligned float4 + one scalar  ->  8 LDG per 4 entries.
__global__ __launch_bounds__(132)
void fill_oct_kernel(const float* __restrict__ density, int b_base)
{
    const int tc = threadIdx.x;                      // x-chunk 0..32 (xb = 4*tc)
    const int yp = blockIdx.x * 4 + threadIdx.y;     // 0..131
    if (yp >= PD) return;
    const int zp = blockIdx.y;                       // 0..129
    const int b  = b_base + blockIdx.z;

    const int xb = tc * 4;
    const int y0 = yp - 1, z0 = zp - 1;
    const float* volb = density + (size_t)b * L * L * L;

    // Window w[dz][dy][0..4] = v(xb-1 .. xb+3) for each of the 4 (y,z) rows.
    float w[2][2][5];
    #pragma unroll
    for (int dz = 0; dz < 2; ++dz) {
        const int z = z0 + dz;
        const bool vz = (unsigned)z < (unsigned)L;
        #pragma unroll
        for (int dy = 0; dy < 2; ++dy) {
            const int y = y0 + dy;
            const bool vr = vz && ((unsigned)y < (unsigned)L);
            const float* row = volb + ((size_t)(vz ? z : 0) * L + (vr ? y : 0)) * L;
            float4 q = make_float4(0.f, 0.f, 0.f, 0.f);
            float lf = 0.f;
            if (vr) {
                if (xb <= L - 4) q = __ldg((const float4*)(row + xb)); // aligned
                if (xb >= 1)     lf = __ldg(row + xb - 1);
            }
            w[dz][dy][0] = lf;
            w[dz][dy][1] = q.x; w[dz][dy][2] = q.y;
            w[dz][dy][3] = q.z; w[dz][dy][4] = q.w;
        }
    }

    uint4* dst = &g_oct[b][((size_t)zp * PD + yp) * PD + xb];
    #pragma unroll
    for (int s = 0; s < 4; ++s) {
        if (xb + s < PD) {
            uint4 e;
            e.x = pack2(w[0][0][s], w[0][0][s + 1]);
            e.y = pack2(w[0][1][s], w[0][1][s + 1]);
            e.z = pack2(w[1][0][s], w[1][0][s + 1]);
            e.w = pack2(w[1][1][s], w[1][1][s + 1]);
            dst[s] = e;
        }
    }
}

__global__ __launch_bounds__(128)
void proj_kernel(const float* __restrict__ rot,
                 float* __restrict__ out, int bq_base)
{
    const int bq = bq_base + blockIdx.y;
    const int b  = bq >> 3;

    const float* R = rot + bq * 9;
    const float R00 = R[0], R01 = R[1], R02 = R[2];   // i-step
    const float R10 = R[3], R11 = R[4], R12 = R[5];   // j-step
    const float R20 = R[6], R21 = R[7], R22 = R[8];   // k-step (ray dir)

    // Lanes walk the step direction with the smaller (y,z) footprint.
    const bool lanes_j = fmaxf(fabsf(R11), fabsf(R12)) < fmaxf(fabsf(R01), fabsf(R02));
    const int i = lanes_j ? blockIdx.x : threadIdx.x;
    const int j = lanes_j ? threadIdx.x : blockIdx.x;

    const uint4* __restrict__ oct = g_oct[b];
    const int ZIDX = PV - 1;   // cell (129,129,129): all corners zero

    const float bx = fmaf((float)i, R00, fmaf((float)j, R10, 63.5f * (1.0f - (R00 + R10 + R20))));
    const float by = fmaf((float)i, R01, fmaf((float)j, R11, 63.5f * (1.0f - (R01 + R11 + R21))));
    const float bz = fmaf((float)i, R02, fmaf((float)j, R12, 63.5f * (1.0f - (R02 + R12 + R22))));

    // Ray-box clip (perf only; sentinel makes all iterations safe & correct).
    float kmin = 0.0f, kmax = 127.0f;
    {
        #pragma unroll
        for (int m = 0; m < 3; ++m) {
            const float bm = (m == 0) ? bx : (m == 1) ? by : bz;
            const float rm = (m == 0) ? R20 : (m == 1) ? R21 : R22;
            if (fabsf(rm) > 1e-9f) {
                const float inv = 1.0f / rm;
                const float t0 = (-1.0f - bm) * inv;
                const float t1 = (129.0f - bm) * inv;
                kmin = fmaxf(kmin, fminf(t0, t1));
                kmax = fminf(kmax, fmaxf(t0, t1));
            } else if (bm <= -1.0f || bm >= 129.0f) {
                kmax = -1.0f;
            }
        }
    }
    const int k0 = max(0,   (int)floorf(kmin));
    const int k1 = min(127, (int)ceilf(kmax));

    float acc = 0.0f;

    #pragma unroll 4
    for (int k = k0; k <= k1; ++k) {
        const float kf = (float)k;
        const float px = fmaf(kf, R20, bx);
        const float py = fmaf(kf, R21, by);
        const float pz = fmaf(kf, R22, bz);

        const float fx0 = floorf(px), fy0 = floorf(py), fz0 = floorf(pz);
        const int xp = (int)fx0 + 1;
        const int yp = (int)fy0 + 1;
        const int zp = (int)fz0 + 1;
        const float fx = px - fx0, fy = py - fy0, fz = pz - fz0;

        // Branch-free: out-of-range samples read the all-zero sentinel cell.
        const unsigned mx = max(max((unsigned)xp, (unsigned)yp), (unsigned)zp);
        int e = (zp * PD + yp) * PD + xp;
        e = (mx <= 129u) ? e : ZIDX;

        const uint4 r = __ldg(oct + e);
        const float2 f00 = __half22float2(*reinterpret_cast<const __half2*>(&r.x));
        const float2 f01 = __half22float2(*reinterpret_cast<const __half2*>(&r.y));
        const float2 f10 = __half22float2(*reinterpret_cast<const __half2*>(&r.z));
        const float2 f11 = __half22float2(*reinterpret_cast<const __half2*>(&r.w));

        const float cx00 = fmaf(fx, f00.y - f00.x, f00.x);
        const float cx10 = fmaf(fx, f01.y - f01.x, f01.x);
        const float c0   = fmaf(fy, cx10 - cx00, cx00);
        const float cx01 = fmaf(fx, f10.y - f10.x, f10.x);
        const float cx11 = fmaf(fx, f11.y - f11.x, f11.x);
        const float c1   = fmaf(fy, cx11 - cx01, cx01);
        acc += fmaf(fz, c1 - c0, c0);
    }

    out[((size_t)bq * L + j) * L + i] = acc;
}

extern "C" void kernel_launch(void* const* d_in, const int* in_sizes, int n_in,
                              void* d_out, int out_size)
{
    const float* density = (const float*)d_in[0];   // (4,128,128,128)
    const float* rot     = (const float*)d_in[1];   // (4,8,3,3)
    float* out           = (float*)d_out;           // (4,8,128,128)

    // Phase volume pairs: each phase's 70MB oct working set stays L2-resident.
    dim3 fgrid(33, PD, 2);        // yp-tiles, zp, b
    dim3 fblock(33, 4);           // x-chunks, yp-in-tile
    dim3 pgrid(L, 16);

    fill_oct_kernel<<<fgrid, fblock>>>(density, 0);
    proj_kernel<<<pgrid, 128>>>(rot, out, 0);
    fill_oct_kernel<<<fgrid, fblock>>>(density, 2);
    proj_kernel<<<pgrid, 128>>>(rot, out, 16);
}